// round 5
// baseline (speedup 1.0000x reference)
#include <cuda_runtime.h>
#include <cuda_bf16.h>
#include <math.h>

#define BATCH 16384
#define KDIM 128
#define CLS 32
#define PL 132             // sS pitch (float4-aligned)
#define PW 68              // 64-block buffer pitch
#define P3 36              // 32-block buffer pitch
#define RCHUNK 8
#define ROWS_PER_CHUNK (BATCH / RCHUNK)   // 2048

// ---------------- scratch (device globals: allocation-free) ----------------
__device__ float g_sum[CLS * KDIM];
__device__ int   g_cnt[CLS];
__device__ int   g_first[CLS];
__device__ float g_G[CLS * KDIM * KDIM];    // per-class Gram sums
__device__ float g_S[CLS * KDIM * KDIM];    // per-class scatter+I
__device__ float g_inv[CLS * KDIM * KDIM];  // per-class inverse
__device__ float g_mu[CLS * KDIM];
__device__ float g_ld2[CLS];

// ---------------- K0: zero scratch + output ----------------
__global__ void k_init(float* out) {
    int i = blockIdx.x * blockDim.x + threadIdx.x;
    if (i < CLS * KDIM * KDIM) g_G[i] = 0.0f;
    if (i < CLS * KDIM) g_sum[i] = 0.0f;
    if (i < CLS) { g_cnt[i] = 0; g_first[i] = BATCH; }
    if (i == 0) out[0] = 0.0f;
}

// ---------------- K1: class sums, counts, first occurrence ----------------
__global__ void k_sums(const float* __restrict__ feat, const int* __restrict__ lab) {
    __shared__ float ssum[CLS * KDIM];   // 16 KB
    __shared__ int   scnt[CLS];
    int tid = threadIdx.x;               // 256 threads
    for (int i = tid; i < CLS * KDIM; i += 256) ssum[i] = 0.0f;
    if (tid < CLS) scnt[tid] = 0;
    __syncthreads();

    int warp = tid >> 5, lane = tid & 31;
    int r0 = blockIdx.x * 256 + warp * 32;   // 64 blocks x 256 rows
    for (int r = r0; r < r0 + 32; r++) {
        int c = lab[r];
        if (lane == 0) { atomicAdd(&scnt[c], 1); atomicMin(&g_first[c], r); }
        float4 v = ((const float4*)(feat + (size_t)r * KDIM))[lane];
        float* dst = &ssum[c * KDIM + lane * 4];
        atomicAdd(dst + 0, v.x);
        atomicAdd(dst + 1, v.y);
        atomicAdd(dst + 2, v.z);
        atomicAdd(dst + 3, v.w);
    }
    __syncthreads();
    for (int i = tid; i < CLS * KDIM; i += 256) atomicAdd(&g_sum[i], ssum[i]);
    if (tid < CLS) atomicAdd(&g_cnt[tid], scnt[tid]);
}

// ---------------- K2: per-class Gram accumulation G_c = sum x x^T ----------
__global__ __launch_bounds__(256) void k_scatter(const float* __restrict__ feat,
                                                 const int* __restrict__ lab) {
    const int c = blockIdx.y;
    const int chunk = blockIdx.x;
    const int R0 = chunk * ROWS_PER_CHUNK;
    __shared__ int s_idx[ROWS_PER_CHUNK];
    __shared__ int s_n;
    __shared__ __align__(16) float s_x[16][KDIM];
    int tid = threadIdx.x;
    if (tid == 0) s_n = 0;
    __syncthreads();

    for (int r = R0 + tid; r < R0 + ROWS_PER_CHUNK; r += 256) {
        if (lab[r] == c) { int p = atomicAdd(&s_n, 1); s_idx[p] = r; }
    }
    __syncthreads();
    int n = s_n;

    float acc[8][8];
#pragma unroll
    for (int u = 0; u < 8; u++)
#pragma unroll
        for (int v = 0; v < 8; v++) acc[u][v] = 0.0f;

    int ty = tid >> 4, tx = tid & 15;

    for (int t = 0; t < n; t += 16) {
        int m = min(16, n - t);
        for (int i = tid; i < m * 32; i += 256) {
            int rr = i >> 5, q = i & 31;
            ((float4*)s_x[rr])[q] =
                ((const float4*)(feat + (size_t)s_idx[t + rr] * KDIM))[q];
        }
        __syncthreads();
        for (int e = 0; e < m; e++) {
            float a[8], b[8];
#pragma unroll
            for (int u = 0; u < 8; u++) { a[u] = s_x[e][ty * 8 + u]; b[u] = s_x[e][tx * 8 + u]; }
#pragma unroll
            for (int u = 0; u < 8; u++)
#pragma unroll
                for (int v = 0; v < 8; v++) acc[u][v] = fmaf(a[u], b[v], acc[u][v]);
        }
        __syncthreads();
    }

    if (n > 0) {
        float* G = g_G + (size_t)c * KDIM * KDIM;
#pragma unroll
        for (int u = 0; u < 8; u++)
#pragma unroll
            for (int v = 0; v < 8; v++)
                atomicAdd(&G[(ty * 8 + u) * KDIM + (tx * 8 + v)], acc[u][v]);
    }
}

// ---------------- warp Gauss-Jordan inverse of SPD 32x32 (in-place) --------
// One warp; lane L holds row L in registers. Accumulates log2(det) (1 log2/lane).
__device__ __forceinline__ void gj32(float* M, int P, float* ldacc) {
    const int lane = threadIdx.x & 31;
    float y[32];
#pragma unroll
    for (int m = 0; m < 32; m++) y[m] = M[lane * P + m];
    float ld = 0.0f;
#pragma unroll
    for (int j = 0; j < 32; j++) {
        float pj = __shfl_sync(0xffffffffu, y[j], j);
        float r = __fdividef(1.0f, pj);
        float c = y[j];
        if (lane == j) {
            ld = log2f(pj);
#pragma unroll
            for (int m = 0; m < 32; m++) y[m] *= r;
            y[j] = r;
        }
#pragma unroll
        for (int m = 0; m < 32; m++) {
            float rowj = __shfl_sync(0xffffffffu, y[m], j);
            if (lane != j && m != j) y[m] -= c * rowj;
        }
        if (lane != j) y[j] = -c * r;
    }
#pragma unroll
    for (int m = 0; m < 32; m++) M[lane * P + m] = y[m];
#pragma unroll
    for (int o = 16; o; o >>= 1) ld += __shfl_xor_sync(0xffffffffu, ld, o);
    if (lane == 0) *ldacc += ld;
}

// ---------------- smem GEMM: O = c0s*C0 + sgn * op(P)·Q  (256 threads) -----
// Vectorized: k-chunks of 4, float4 operand loads. Pitches must be %4==0.
// TRA=false: P[i][m];  TRA=true: P[m][i].  Q always Q[m][j].
template<int N, bool TRA>
__device__ __forceinline__ void sgemm(const float* __restrict__ P, int pp,
                                      const float* __restrict__ Q, int pq,
                                      float* __restrict__ O, int po,
                                      const float* __restrict__ C0, int pc,
                                      float c0s, float sgn) {
    constexpr int RT = (N == 64) ? 4 : 1;    // row tile
    constexpr int CG = N / 4;                // col groups
    const int r0 = (threadIdx.x / CG) * RT;
    const int c0 = (threadIdx.x % CG) * 4;
    float acc[RT][4];
#pragma unroll
    for (int u = 0; u < RT; u++)
#pragma unroll
        for (int v = 0; v < 4; v++) acc[u][v] = 0.0f;

#pragma unroll
    for (int m = 0; m < N; m += 4) {
        float4 b4[4];
#pragma unroll
        for (int mm = 0; mm < 4; mm++)
            b4[mm] = *(const float4*)&Q[(m + mm) * pq + c0];
        float a[RT][4];
        if (TRA) {
            if (RT == 4) {
#pragma unroll
                for (int mm = 0; mm < 4; mm++) {
                    float4 t = *(const float4*)&P[(m + mm) * pp + r0];
                    a[0][mm] = t.x; a[1][mm] = t.y; a[2][mm] = t.z; a[3][mm] = t.w;
                }
            } else {
#pragma unroll
                for (int mm = 0; mm < 4; mm++) a[0][mm] = P[(m + mm) * pp + r0];
            }
        } else {
#pragma unroll
            for (int u = 0; u < RT; u++) {
                float4 t = *(const float4*)&P[(r0 + u) * pp + m];
                a[u][0] = t.x; a[u][1] = t.y; a[u][2] = t.z; a[u][3] = t.w;
            }
        }
#pragma unroll
        for (int u = 0; u < RT; u++)
#pragma unroll
            for (int mm = 0; mm < 4; mm++) {
                acc[u][0] = fmaf(a[u][mm], b4[mm].x, acc[u][0]);
                acc[u][1] = fmaf(a[u][mm], b4[mm].y, acc[u][1]);
                acc[u][2] = fmaf(a[u][mm], b4[mm].z, acc[u][2]);
                acc[u][3] = fmaf(a[u][mm], b4[mm].w, acc[u][3]);
            }
    }

#pragma unroll
    for (int u = 0; u < RT; u++) {
        float4 o;
        o.x = sgn * acc[u][0]; o.y = sgn * acc[u][1];
        o.z = sgn * acc[u][2]; o.w = sgn * acc[u][3];
        if (C0) {
            float4 cc = *(const float4*)&C0[(r0 + u) * pc + c0];
            o.x += c0s * cc.x; o.y += c0s * cc.y;
            o.z += c0s * cc.z; o.w += c0s * cc.w;
        }
        *(float4*)&O[(r0 + u) * po + c0] = o;
    }
}

// ---------------- 64x64 SPD inverse via one-level Schur (in place) ---------
__device__ void inv64(float* M, int pm, float* ldacc,
                      float* w, float* t, float* u) {
    if (threadIdx.x < 32) gj32(M, pm, ldacc);               // a -> inva
    __syncthreads();
    sgemm<32, false>(M + 32 * pm, pm, M, pm, w, P3, (const float*)0, 0, 0.f, 1.f);  // w = b·inva
    __syncthreads();
    sgemm<32, false>(w, P3, M + 32, pm, t, P3, M + 32 * pm + 32, pm, 1.f, -1.f);    // t = c - w·b^T
    __syncthreads();
    if (threadIdx.x < 32) gj32(t, P3, ldacc);               // t -> invt
    __syncthreads();
    sgemm<32, false>(t, P3, w, P3, u, P3, (const float*)0, 0, 0.f, 1.f);            // u = invt·w
    __syncthreads();
    sgemm<32, true>(w, P3, u, P3, M, pm, M, pm, 1.f, 1.f);  // M00 = inva + w^T·u
    for (int idx = threadIdx.x; idx < 32 * 32; idx += 256) {
        int i = idx >> 5, j = idx & 31;
        M[(32 + i) * pm + 32 + j] = t[i * P3 + j];
        M[(32 + i) * pm + j]      = -u[i * P3 + j];
        M[i * pm + 32 + j]        = -u[j * P3 + i];
    }
    __syncthreads();
}

// ---------------- K3: per-class S, S^{-1} (Schur D&C), log2det -------------
__global__ __launch_bounds__(256, 1) void k_sinv() {
    extern __shared__ float sm[];
    float* sS  = sm;                       // 128 * PL
    float* sW  = sS + KDIM * PL;           // 64 * PW
    float* sT  = sW + 64 * PW;             // 64 * PW
    float* sU  = sT + 64 * PW;             // 64 * PW
    float* s3a = sU + 64 * PW;             // 32 * P3
    float* s3b = s3a + 32 * P3;
    float* s3c = s3b + 32 * P3;
    __shared__ float s_mu[KDIM];
    __shared__ float s_ld;

    const int c = blockIdx.x, tid = threadIdx.x;

    float n = (float)g_cnt[c];
    float rn = 1.0f / n;
    if (tid < KDIM) {
        float m = g_sum[c * KDIM + tid] * rn;
        s_mu[tid] = m;
        g_mu[c * KDIM + tid] = m;
    }
    if (tid == 0) s_ld = 0.0f;
    __syncthreads();

    // build S = G/n - mu mu^T + I (into smem + g_S)
    const float* G = g_G + (size_t)c * KDIM * KDIM;
    float* Sg = g_S + (size_t)c * KDIM * KDIM;
    for (int idx = tid; idx < KDIM * KDIM; idx += 256) {
        int a = idx >> 7, b = idx & 127;
        float s = G[idx] * rn - s_mu[a] * s_mu[b] + (a == b ? 1.0f : 0.0f);
        sS[a * PL + b] = s;
        Sg[idx] = s;
    }
    __syncthreads();

    // ---- S = [[A, Bt],[B, C]] ; two-level Schur inverse ----
    inv64(sS, PL, &s_ld, s3a, s3b, s3c);                     // A -> invA
    sgemm<64, false>(sS + 64 * PL, PL, sS, PL, sW, PW, (const float*)0, 0, 0.f, 1.f); // W = B·invA
    __syncthreads();
    sgemm<64, false>(sW, PW, sS + 64, PL, sT, PW, sS + 64 * PL + 64, PL, 1.f, -1.f);  // T = C - W·B^T
    __syncthreads();
    inv64(sT, PW, &s_ld, s3a, s3b, s3c);                     // T -> invT
    sgemm<64, false>(sT, PW, sW, PW, sU, PW, (const float*)0, 0, 0.f, 1.f);           // U = invT·W
    __syncthreads();
    sgemm<64, true>(sW, PW, sU, PW, sS, PL, sS, PL, 1.f, 1.f);  // top-left = invA + W^T·U
    for (int idx = tid; idx < 64 * 64; idx += 256) {
        int i = idx >> 6, j = idx & 63;
        sS[(64 + i) * PL + 64 + j] = sT[i * PW + j];
        sS[(64 + i) * PL + j]      = -sU[i * PW + j];
        sS[i * PL + 64 + j]        = -sU[j * PW + i];
    }
    __syncthreads();

    // dump inverse + logdet
    float* Ig = g_inv + (size_t)c * KDIM * KDIM;
    for (int idx = tid; idx < KDIM * KDIM / 4; idx += 256) {
        int a = idx >> 5, b4 = (idx & 31) << 2;
        *(float4*)&Ig[a * KDIM + b4] = *(const float4*)&sS[a * PL + b4];
    }
    if (tid == 0) g_ld2[c] = s_ld;
}

// ---------------- K4: pairwise KL + mask + final reduction -----------------
__global__ void k_final(float* out) {
    int i = blockIdx.x >> 5, j = blockIdx.x & 31;
    int tid = threadIdx.x;
    __shared__ float sv[KDIM];
    __shared__ float2 sred[256];
    __shared__ int smask;

    if (tid == 0) {
        int fi = g_first[i], fj = g_first[j], ri = 0, rj = 0;
        for (int c = 0; c < CLS; c++) { int f = g_first[c]; ri += (f < fi); rj += (f < fj); }
        smask = (ri <= CLS - 2) && (rj >= 1);
    }
    if (tid < KDIM) sv[tid] = g_mu[i * KDIM + tid] - g_mu[j * KDIM + tid];
    __syncthreads();

    float tr = 0.0f, qd = 0.0f;
    if (smask) {
        const float* Sp = g_S + (size_t)i * KDIM * KDIM;
        const float* Ip = g_inv + (size_t)j * KDIM * KDIM;
        for (int idx = tid; idx < KDIM * KDIM; idx += 256) {
            float w = Ip[idx];
            tr += w * Sp[idx];
            qd += w * sv[idx >> 7] * sv[idx & 127];
        }
    }
    sred[tid] = make_float2(tr, qd);
    __syncthreads();
    for (int s = 128; s; s >>= 1) {
        if (tid < s) { sred[tid].x += sred[tid + s].x; sred[tid].y += sred[tid + s].y; }
        __syncthreads();
    }
    if (tid == 0 && smask) {
        float kl = 0.5f * ((g_ld2[j] - g_ld2[i]) - (float)KDIM + sred[0].y + sred[0].x);
        atomicAdd(out, kl);
    }

    if (blockIdx.x == 0) {
        __syncthreads();
        float m2 = 0.0f;
        for (int idx = tid; idx < CLS * KDIM; idx += 256) { float m = g_mu[idx]; m2 += m * m; }
        sred[tid].x = m2;
        __syncthreads();
        for (int s = 128; s; s >>= 1) { if (tid < s) sred[tid].x += sred[tid + s].x; __syncthreads(); }
        if (tid == 0) atomicAdd(out, -sred[0].x);
    }
}

// ---------------- launch ----------------
extern "C" void kernel_launch(void* const* d_in, const int* in_sizes, int n_in,
                              void* d_out, int out_size) {
    const float* feat = (const float*)d_in[0];
    const int*   lab  = (const int*)d_in[1];
    float* out = (float*)d_out;

    const int SINV_SMEM = (KDIM * PL + 3 * 64 * PW + 3 * 32 * P3) * (int)sizeof(float); // 133632
    cudaFuncSetAttribute(k_sinv, cudaFuncAttributeMaxDynamicSharedMemorySize, SINV_SMEM);

    k_init<<<(CLS * KDIM * KDIM + 255) / 256, 256>>>(out);
    k_sums<<<BATCH / 256, 256>>>(feat, lab);
    k_scatter<<<dim3(RCHUNK, CLS), 256>>>(feat, lab);
    k_sinv<<<CLS, 256, SINV_SMEM>>>();
    k_final<<<CLS * CLS, 256>>>(out);
}